// round 12
// baseline (speedup 1.0000x reference)
#include <cuda_runtime.h>
#include <cuda_bf16.h>

#define NBLK 128
#define NTHR 512
#define BB   128
#define TT   512
#define PREDN 24
#define FF   16
#define LL   8
#define HH   1024
#define FROWS (TT + PREDN - 1)

typedef unsigned int uint;

#define BARG1() asm volatile("bar.sync 1, 256;" ::: "memory")
#define BARG2() asm volatile("bar.sync 2, 256;" ::: "memory")

// ---------------- persistent device scratch ---------------------------------
__device__ uint4 g_A0[2][2][8 * 64 * 32];   // hidden states, MMA A-frag order
__device__ uint4 g_A1[2][2][8 * 64 * 32];
__device__ uint4 g_B[4][NBLK][3][32][2][32]; // [mat][bid][nf][hc][pl][ln]
__device__ float g_p[BB * LL];
__device__ unsigned g_count = 0;
__device__ unsigned g_gen = 0;

// ---------------- grid barrier ----------------------------------------------
__device__ __forceinline__ void gbar() {
    __syncthreads();
    if (threadIdx.x == 0) {
        __threadfence();
        volatile unsigned* vg = &g_gen;
        unsigned g = *vg;
        if (atomicAdd(&g_count, 1u) == NBLK - 1) {
            g_count = 0;
            __threadfence();
            *vg = g + 1;
        } else {
            while (*vg == g) {}
        }
        __threadfence();
    }
    __syncthreads();
}

// ---------------- 2B coherent global ld/st ----------------------------------
__device__ __forceinline__ unsigned short ldcg_u16(const void* p) {
    unsigned short v;
    asm volatile("ld.global.cg.u16 %0, [%1];" : "=h"(v) : "l"(p));
    return v;
}
__device__ __forceinline__ void stcg_u16(void* p, unsigned short v) {
    asm volatile("st.global.cg.u16 [%0], %1;" :: "l"(p), "h"(v));
}

// ---------------- h element <-> fragment-layout mapping ----------------------
__device__ __forceinline__ int h_off(int b, int u) {
    int rg = b >> 4, r = b & 15, kp = u & 15, kg = u >> 4;
    int ireg = (r >> 3) + ((kp >> 3) << 1);
    int ln = (r & 7) * 4 + ((kp & 7) >> 1);
    return ((rg * 64 + kg) * 32 + ln) * 16 + ireg * 4 + (kp & 1) * 2;
}
__device__ __forceinline__ void store_h(uint4* Ph, uint4* Pl, int b, int u, float v) {
    __nv_bfloat16 hi = __float2bfloat16(v);
    __nv_bfloat16 lo = __float2bfloat16(v - __bfloat162float(hi));
    int off = h_off(b, u);
    stcg_u16((char*)Ph + off, __bfloat16_as_ushort(hi));
    stcg_u16((char*)Pl + off, __bfloat16_as_ushort(lo));
}
__device__ __forceinline__ float load_h(const uint4* Ph, const uint4* Pl, int b, int u) {
    int off = h_off(b, u);
    float hi = __bfloat162float(__ushort_as_bfloat16(ldcg_u16((const char*)Ph + off)));
    float lo = __bfloat162float(__ushort_as_bfloat16(ldcg_u16((const char*)Pl + off)));
    return hi + lo;
}

// ---------------- HMMA m16n8k16 bf16 -> f32 ----------------------------------
__device__ __forceinline__ void mma16816(float* c, const uint* a, uint b0, uint b1) {
    asm volatile(
        "mma.sync.aligned.m16n8k16.row.col.f32.bf16.bf16.f32 "
        "{%0,%1,%2,%3}, {%4,%5,%6,%7}, {%8,%9}, {%0,%1,%2,%3};"
        : "+f"(c[0]), "+f"(c[1]), "+f"(c[2]), "+f"(c[3])
        : "r"(a[0]), "r"(a[1]), "r"(a[2]), "r"(a[3]), "r"(b0), "r"(b1));
}

// ---------------- cp.async staging --------------------------------------------
// group A ring slot: 1536 uint4, layout ((set*4+hcg)*6 + nf*2+pl)*32 + ln
__device__ __forceinline__ void issue0(const uint4* __restrict__ B0,
                                       const uint4* __restrict__ B1,
                                       const int* offs, int hc0, uint dst, int t) {
    const uint4* base = ((t < 128) ? B0 : B1) + hc0 * 64;
    uint d = dst + t * 96;
    #pragma unroll
    for (int j = 0; j < 6; j++)
        asm volatile("cp.async.cg.shared.global [%0], [%1], 16;"
                     :: "r"(d + j * 16), "l"(base + offs[j]) : "memory");
}
// group B ring slot: 768 uint4, layout (hcg*6 + nf*2+pl)*32 + ln; 256 stagers x3
__device__ __forceinline__ void issue1(const uint4* __restrict__ B,
                                       const int* offs1, int hc0, uint dst, int s1) {
    const uint4* base = B + hc0 * 64;
    uint d = dst + s1 * 48;
    #pragma unroll
    for (int j = 0; j < 3; j++)
        asm volatile("cp.async.cg.shared.global [%0], [%1], 16;"
                     :: "r"(d + j * 16), "l"(base + offs1[j]) : "memory");
}

// ---------------- group A: dual GEMM (8 warps, threads 0-255) ------------------
// Warp w rows [16w,16w+16), all 24 cols, K=1024. accS <- B0 (set0), accR <- B1.
__device__ void gemm_dual(const uint4* __restrict__ Ah, const uint4* __restrict__ Al,
                          const uint4* __restrict__ B0, const uint4* __restrict__ B1,
                          const int* offs, uint4* __restrict__ sB, uint sb_addr,
                          int w, int lane, int t,
                          float accS[3][4], float accR[3][4]) {
    #pragma unroll
    for (int nf = 0; nf < 3; nf++)
        #pragma unroll
        for (int i = 0; i < 4; i++) { accS[nf][i] = 0.f; accR[nf][i] = 0.f; }

    const uint4* Abh = Ah + w * 2048 + lane;
    const uint4* Abl = Al + w * 2048 + lane;

    BARG1();
    issue0(B0, B1, offs, 0, sb_addr, t);
    asm volatile("cp.async.commit_group;" ::: "memory");
    issue0(B0, B1, offs, 4, sb_addr + 24576, t);
    asm volatile("cp.async.commit_group;" ::: "memory");

    uint4 fah[4][2], fal[4][2];
    #pragma unroll
    for (int j = 0; j < 4; j++) {
        fah[j][0] = __ldcg(Abh + j * 64);   fah[j][1] = __ldcg(Abh + j * 64 + 32);
        fal[j][0] = __ldcg(Abl + j * 64);   fal[j][1] = __ldcg(Abl + j * 64 + 32);
    }

    #pragma unroll 1
    for (int g = 0; g < 8; g++) {
        asm volatile("cp.async.wait_group 1;" ::: "memory");
        BARG1();
        if (g + 2 < 8) issue0(B0, B1, offs, (g + 2) * 4, sb_addr + ((g + 2) % 3) * 24576, t);
        asm volatile("cp.async.commit_group;" ::: "memory");
        const uint4* sbuf = sB + (g % 3) * 1536;
        #pragma unroll
        for (int j = 0; j < 4; j++) {
            #pragma unroll
            for (int s = 0; s < 2; s++) {
                float (*acc)[4] = s ? accR : accS;
                #pragma unroll
                for (int nf = 0; nf < 3; nf++) {
                    uint4 BH = sbuf[((s * 4 + j) * 6 + nf * 2) * 32 + lane];
                    uint4 BL = sbuf[((s * 4 + j) * 6 + nf * 2 + 1) * 32 + lane];
                    const uint* a0h = (const uint*)&fah[j][0];
                    const uint* a0l = (const uint*)&fal[j][0];
                    const uint* a1h = (const uint*)&fah[j][1];
                    const uint* a1l = (const uint*)&fal[j][1];
                    mma16816(acc[nf], a0h, BH.x, BH.y);
                    mma16816(acc[nf], a0l, BH.x, BH.y);
                    mma16816(acc[nf], a0h, BL.x, BL.y);
                    mma16816(acc[nf], a1h, BH.z, BH.w);
                    mma16816(acc[nf], a1l, BH.z, BH.w);
                    mma16816(acc[nf], a1h, BL.z, BL.w);
                }
            }
            int nhc = 4 * g + 4 + j;
            if (nhc < 32) {
                fah[j][0] = __ldcg(Abh + nhc * 64);  fah[j][1] = __ldcg(Abh + nhc * 64 + 32);
                fal[j][0] = __ldcg(Abl + nhc * 64);  fal[j][1] = __ldcg(Abl + nhc * 64 + 32);
            }
        }
    }
}

// ---------------- group B: single GEMM (8 warps, threads 256-511) --------------
// Warp w1 owns m-tile w1 (rows [16w1,16w1+16)), all 24 cols, K=1024.
__device__ void gemm_single(const uint4* __restrict__ Ah, const uint4* __restrict__ Al,
                            const uint4* __restrict__ Bsrc, const int* offs1,
                            uint4* __restrict__ sR, uint sr_addr,
                            int w1, int lane, int s1, float acc[3][4]) {
    #pragma unroll
    for (int nf = 0; nf < 3; nf++)
        #pragma unroll
        for (int i = 0; i < 4; i++) acc[nf][i] = 0.f;

    const uint4* Abh = Ah + w1 * 2048 + lane;
    const uint4* Abl = Al + w1 * 2048 + lane;

    BARG2();
    issue1(Bsrc, offs1, 0, sr_addr, s1);
    asm volatile("cp.async.commit_group;" ::: "memory");
    issue1(Bsrc, offs1, 4, sr_addr + 12288, s1);
    asm volatile("cp.async.commit_group;" ::: "memory");

    uint4 fah[4][2], fal[4][2];
    #pragma unroll
    for (int j = 0; j < 4; j++) {
        fah[j][0] = __ldcg(Abh + j * 64);   fah[j][1] = __ldcg(Abh + j * 64 + 32);
        fal[j][0] = __ldcg(Abl + j * 64);   fal[j][1] = __ldcg(Abl + j * 64 + 32);
    }

    #pragma unroll 1
    for (int g = 0; g < 8; g++) {
        asm volatile("cp.async.wait_group 1;" ::: "memory");
        BARG2();
        if (g + 2 < 8) issue1(Bsrc, offs1, (g + 2) * 4, sr_addr + ((g + 2) % 3) * 12288, s1);
        asm volatile("cp.async.commit_group;" ::: "memory");
        const uint4* sbuf = sR + (g % 3) * 768;
        #pragma unroll
        for (int j = 0; j < 4; j++) {
            #pragma unroll
            for (int nf = 0; nf < 3; nf++) {
                uint4 BH = sbuf[(j * 6 + nf * 2) * 32 + lane];
                uint4 BL = sbuf[(j * 6 + nf * 2 + 1) * 32 + lane];
                const uint* a0h = (const uint*)&fah[j][0];
                const uint* a0l = (const uint*)&fal[j][0];
                const uint* a1h = (const uint*)&fah[j][1];
                const uint* a1l = (const uint*)&fal[j][1];
                mma16816(acc[nf], a0h, BH.x, BH.y);
                mma16816(acc[nf], a0l, BH.x, BH.y);
                mma16816(acc[nf], a0h, BL.x, BL.y);
                mma16816(acc[nf], a1h, BH.z, BH.w);
                mma16816(acc[nf], a1l, BH.z, BH.w);
                mma16816(acc[nf], a1h, BL.z, BL.w);
            }
            int nhc = 4 * g + 4 + j;
            if (nhc < 32) {
                fah[j][0] = __ldcg(Abh + nhc * 64);  fah[j][1] = __ldcg(Abh + nhc * 64 + 32);
                fal[j][0] = __ldcg(Abl + nhc * 64);  fal[j][1] = __ldcg(Abl + nhc * 64 + 32);
            }
        }
    }
}

// ---------------- in-register GRU update (group A, per MMA lane) ----------------
// sb: per-u bias table {bir+bhr, biz+bhz, bin, bhn} x 8 u-columns
__device__ __forceinline__ float sigf(float x) { return 1.f / (1.f + __expf(-x)); }

__device__ __forceinline__ void upd_lane(const float gi[3][4], const float gh[3][4],
                                         const float* __restrict__ sb,
                                         int u0, int w, int lane,
                                         const uint4* Phc, const uint4* Plc,
                                         uint4* Phn, uint4* Pln) {
    int r0 = w * 16 + (lane >> 2);
    int c2 = (lane & 3) * 2;
    float v[2][4];
    #pragma unroll
    for (int q = 0; q < 2; q++) {
        float4 bv = *reinterpret_cast<const float4*>(sb + (c2 + q) * 4);
        v[q][0] = bv.x; v[q][1] = bv.y; v[q][2] = bv.z; v[q][3] = bv.w;
    }
    #pragma unroll
    for (int i = 0; i < 4; i++) {
        int b = r0 + (i >> 1) * 8;
        int q = i & 1;
        int jc = u0 + c2 + q;
        float r = sigf(gi[0][i] + gh[0][i] + v[q][0]);
        float z = sigf(gi[1][i] + gh[1][i] + v[q][1]);
        float n = tanhf(gi[2][i] + v[q][2] + r * (gh[2][i] + v[q][3]));
        float ho = Phc ? load_h(Phc, Plc, b, jc) : 0.f;
        store_h(Phn, Pln, b, jc, (1.f - z) * n + z * ho);
    }
}

__device__ __forceinline__ void xproj_lane(const float* __restrict__ sh_x,
                                           const float* __restrict__ sh_wi,
                                           int w, int lane, float ai[3][4]) {
    int r0 = w * 16 + (lane >> 2);
    int c2 = (lane & 3) * 2;
    #pragma unroll
    for (int i = 0; i < 4; i++) {
        int b = r0 + (i >> 1) * 8;
        int u = c2 + (i & 1);
        float a0 = 0.f, a1 = 0.f, a2 = 0.f;
        #pragma unroll
        for (int k = 0; k < 24; k++) {
            float xv = sh_x[b * 25 + k];
            a0 += xv * sh_wi[k * 24 + u];
            a1 += xv * sh_wi[k * 24 + 8 + u];
            a2 += xv * sh_wi[k * 24 + 16 + u];
        }
        ai[0][i] = a0; ai[1][i] = a1; ai[2][i] = a2;
    }
}

// ---------------- misc helpers ------------------------------------------------
__device__ __forceinline__ void fill_bias(const float* __restrict__ bih,
                                          const float* __restrict__ bhh,
                                          int u0, float* __restrict__ sb) {
    if (threadIdx.x < 8) {
        int jc = u0 + threadIdx.x;
        sb[threadIdx.x * 4 + 0] = bih[jc] + bhh[jc];
        sb[threadIdx.x * 4 + 1] = bih[HH + jc] + bhh[HH + jc];
        sb[threadIdx.x * 4 + 2] = bih[2 * HH + jc];
        sb[threadIdx.x * 4 + 3] = bhh[2 * HH + jc];
    }
}

__device__ __forceinline__ void load_wi_slice(const float* __restrict__ Wih, int u0,
                                              float* __restrict__ sh_wi) {
    for (int idx = threadIdx.x; idx < 24 * 24; idx += NTHR) {
        int jl = idx / 24, k = idx % 24;
        int g = jl >> 3, uu = jl & 7;
        sh_wi[k * 24 + jl] = Wih[(long)(g * HH + u0 + uu) * 24 + k];
    }
}

__device__ __forceinline__ void fc_phase(const uint4* Ph, const uint4* Pl,
                                         const float* __restrict__ fcW,
                                         const float* __restrict__ fcb,
                                         float* __restrict__ outp) {
    int b = blockIdx.x;
    int w = threadIdx.x >> 5;
    int lane = threadIdx.x & 31;
    float s = 0.f;
    #pragma unroll
    for (int c = 0; c < 32; c++) {
        int u = c * 32 + lane;
        s += load_h(Ph, Pl, b, u) * fcW[(long)w * HH + u];
    }
    #pragma unroll
    for (int o = 16; o; o >>= 1) s += __shfl_down_sync(0xffffffffu, s, o);
    if (lane == 0) {
        float v = s + fcb[w];
        outp[b * LL + w] = v;
        asm volatile("st.global.cg.f32 [%0], %1;" :: "l"(g_p + b * LL + w), "f"(v));
    }
}

// ---------------- persistent kernel -----------------------------------------
__global__ void __launch_bounds__(NTHR, 1) gru_persistent(
    const float* __restrict__ feats, const float* __restrict__ labels,
    const float* __restrict__ y, const int* __restrict__ teacher,
    const float* __restrict__ eWih0, const float* __restrict__ eWhh0,
    const float* __restrict__ ebih0, const float* __restrict__ ebhh0,
    const float* __restrict__ eWih1, const float* __restrict__ eWhh1,
    const float* __restrict__ ebih1, const float* __restrict__ ebhh1,
    const float* __restrict__ dWih, const float* __restrict__ dWhh,
    const float* __restrict__ dbih, const float* __restrict__ dbhh,
    const float* __restrict__ fcW, const float* __restrict__ fcb,
    float* __restrict__ out)
{
    extern __shared__ __align__(16) unsigned char smem_raw[];
    uint4* sB0   = (uint4*)smem_raw;                        // 73728 B (group A ring)
    uint4* sR1   = (uint4*)(smem_raw + 73728);              // 36864 B (group B ring)
    float* gates = (float*)(smem_raw + 110592);             // 12288 B (gh1 exchange)
    float* sh_x  = (float*)(smem_raw + 122880);             // 12800 B
    float* sh_wi = (float*)(smem_raw + 135680);             // 2304 B
    float* sb_b0 = (float*)(smem_raw + 137984);             // 128 B (layer0/dec bias)
    float* sb_b1 = (float*)(smem_raw + 138112);             // 128 B (layer1 bias)
    const uint sb0_addr = (uint)__cvta_generic_to_shared(sB0);
    const uint sr1_addr = (uint)__cvta_generic_to_shared(sR1);

    const int t = threadIdx.x;
    const int lane = t & 31;
    const int u0 = blockIdx.x * 8;
    const int teach = teacher[0];
    const bool isg0 = (t < 256);
    const int w = t >> 5;            // group A warp id (0-7 when isg0)
    const int w1 = (t - 256) >> 5;   // group B warp id (0-7)
    const int s1 = t - 256;          // group B staging index (0-255)

    // cp.async source offsets
    int offs[6];   // group A (6 per thread)
    int offs1[3];  // group B (3 per thread)
    {
        int s = isg0 ? t : s1;
        #pragma unroll
        for (int j = 0; j < 6; j++) {
            int li = s * 6 + j;
            int ln = li & 31;
            int q = li >> 5;
            int sub = q % 6;
            int hcg = (q / 6) & 3;
            int nf = sub >> 1, pl = sub & 1;
            offs[j] = nf * 2048 + hcg * 64 + pl * 32 + ln;
        }
        #pragma unroll
        for (int j = 0; j < 3; j++) {
            int li = s * 3 + j;
            int ln = li & 31;
            int q = li >> 5;          // 0..23
            int sub = q % 6;
            int hcg = q / 6;          // 0..3
            int nf = sub >> 1, pl = sub & 1;
            offs1[j] = nf * 2048 + hcg * 64 + pl * 32 + ln;
        }
    }

    const uint4* Bb0 = &g_B[0][blockIdx.x][0][0][0][0];   // eWhh0
    const uint4* Bb1 = &g_B[1][blockIdx.x][0][0][0][0];   // eWih1
    const uint4* Bb2 = &g_B[2][blockIdx.x][0][0][0][0];   // eWhh1
    const uint4* Bb3 = &g_B[3][blockIdx.x][0][0][0][0];   // dWhh

    // ---- zero h1 buffer 0 (h1(-1) = 0), both planes ----
    {
        int gid = blockIdx.x * NTHR + t;
        if (gid < 32768) ((uint4*)g_A1)[gid] = make_uint4(0, 0, 0, 0);
    }

    // ---- split + permute weights into fragment order (per-block slice) ----
    {
        const float* Wm[4] = {eWhh0, eWih1, eWhh1, dWhh};
        for (int wdx = t; wdx < 4 * 3 * 32 * 2 * 32; wdx += NTHR) {
            int ln = wdx & 31;
            int pl = (wdx >> 5) & 1;
            int hc = (wdx >> 6) & 31;
            int rest = wdx >> 11;
            int nw = rest % 3, m = rest / 3;
            const float* W = Wm[m];
            int u = ln >> 2;
            long wr = (long)(nw * HH + u0 + u) * HH;
            uint vals[4];
            #pragma unroll
            for (int c = 0; c < 4; c++) {
                int k0 = hc * 32 + (c >> 1) * 16 + (c & 1) * 8 + (ln & 3) * 2;
                float2 xv = *reinterpret_cast<const float2*>(W + wr + k0);
                __nv_bfloat16 h0 = __float2bfloat16(xv.x);
                __nv_bfloat16 h1 = __float2bfloat16(xv.y);
                if (pl) {
                    h0 = __float2bfloat16(xv.x - __bfloat162float(h0));
                    h1 = __float2bfloat16(xv.y - __bfloat162float(h1));
                }
                vals[c] = (uint)__bfloat16_as_ushort(h0) |
                          ((uint)__bfloat16_as_ushort(h1) << 16);
            }
            g_B[m][blockIdx.x][nw][hc][pl][ln] = make_uint4(vals[0], vals[1], vals[2], vals[3]);
        }
    }
    load_wi_slice(eWih0, u0, sh_wi);
    fill_bias(ebih0, ebhh0, u0, sb_b0);
    if (t >= 8 && t < 16) {
        int jc = u0 + t - 8;
        sb_b1[(t - 8) * 4 + 0] = ebih1[jc] + ebhh1[jc];
        sb_b1[(t - 8) * 4 + 1] = ebih1[HH + jc] + ebhh1[HH + jc];
        sb_b1[(t - 8) * 4 + 2] = ebih1[2 * HH + jc];
        sb_b1[(t - 8) * 4 + 3] = ebhh1[2 * HH + jc];
    }

    // ---- prologue: h0(0) = GRU(x(0), h=0) -> g_A0[0] ----
    for (int idx = t; idx < BB * 24; idx += NTHR) {
        int b = idx / 24, k = idx % 24;
        sh_x[b * 25 + k] = (k < FF) ? feats[((long)b * FROWS) * FF + k]
                                    : labels[((long)b * TT) * LL + (k - FF)];
    }
    __syncthreads();
    if (isg0) {
        float ai[3][4], zg[3][4];
        #pragma unroll
        for (int g = 0; g < 3; g++)
            #pragma unroll
            for (int i = 0; i < 4; i++) zg[g][i] = 0.f;
        xproj_lane(sh_x, sh_wi, w, lane, ai);
        upd_lane(ai, zg, sb_b0, u0, w, lane,
                 nullptr, nullptr, g_A0[0][0], g_A0[0][1]);
    }
    gbar();

    // ================= encoder: warp-specialized, 1 gbar/step ================
    for (int step = 0; step < TT; step++) {
        int rb = step & 1, wb = rb ^ 1;

        if (step + 1 < TT) {
            for (int idx = t; idx < BB * 24; idx += NTHR) {
                int b = idx / 24, k = idx % 24;
                sh_x[b * 25 + k] = (k < FF) ? feats[((long)b * FROWS + step + 1) * FF + k]
                                            : labels[((long)b * TT + step + 1) * LL + (k - FF)];
            }
        }

        float accS[3][4], accR[3][4];
        if (isg0) {
            // A = h0(step): accS = Wih1 gates (gi1), accR = Whh0 gates (t+1)
            gemm_dual(g_A0[rb][0], g_A0[rb][1], Bb1, Bb0, offs, sB0, sb0_addr,
                      w, lane, t, accS, accR);
        } else {
            // A = h1(step-1): gh1 = Whh1 gates (1 m-tile/warp)
            float acc[3][4];
            gemm_single(g_A1[rb][0], g_A1[rb][1], Bb2, offs1, sR1, sr1_addr,
                        w1, lane, s1, acc);
            float* gp = gates + (w1 * 32 + lane) * 12;
            #pragma unroll
            for (int nf = 0; nf < 3; nf++)
                #pragma unroll
                for (int i = 0; i < 4; i++) gp[nf * 4 + i] = acc[nf][i];
        }
        __syncthreads();

        if (isg0) {
            float ghl[3][4];
            const float* gp = gates + (w * 32 + lane) * 12;
            #pragma unroll
            for (int nf = 0; nf < 3; nf++)
                #pragma unroll
                for (int i = 0; i < 4; i++) ghl[nf][i] = gp[nf * 4 + i];
            // h1(step) = GRU(gi=accS, gh=ghl, h1_old)
            upd_lane(accS, ghl, sb_b1, u0, w, lane,
                     g_A1[rb][0], g_A1[rb][1], g_A1[wb][0], g_A1[wb][1]);
            // h0(step+1) = GRU(xproj(step+1), gh=accR, h0_old)
            if (step + 1 < TT) {
                float ai[3][4];
                xproj_lane(sh_x, sh_wi, w, lane, ai);
                upd_lane(ai, accR, sb_b0, u0, w, lane,
                         g_A0[rb][0], g_A0[rb][1], g_A0[wb][0], g_A0[wb][1]);
            }
        }
        gbar();
    }

    // ps -> out[0] + seed g_p (final h1 in buffer 0)
    if (isg0) fc_phase(g_A1[0][0], g_A1[0][1], fcW, fcb, out);
    load_wi_slice(dWih, u0, sh_wi);
    __syncthreads();                      // sb_b0 consumers done (encoder finished)
    fill_bias(dbih, dbhh, u0, sb_b0);
    gbar();

    // ================= decoder ==============================================
    for (int s = 0; s < PREDN - 1; s++) {
        int rb = s & 1, wb = rb ^ 1;
        for (int idx = t; idx < BB * 24; idx += NTHR) {
            int b = idx / 24, k = idx % 24;
            float v;
            if (k < FF)      v = feats[((long)b * FROWS + TT + s) * FF + k];
            else if (teach)  v = y[((long)b * (PREDN - 1) + s) * LL + (k - FF)];
            else             v = __ldcg(g_p + b * LL + (k - FF));
            sh_x[b * 25 + k] = v;
        }

        if (!isg0) {
            float acc[3][4];
            gemm_single(g_A1[rb][0], g_A1[rb][1], Bb3, offs1, sR1, sr1_addr,
                        w1, lane, s1, acc);
            float* gp = gates + (w1 * 32 + lane) * 12;
            #pragma unroll
            for (int nf = 0; nf < 3; nf++)
                #pragma unroll
                for (int i = 0; i < 4; i++) gp[nf * 4 + i] = acc[nf][i];
        }
        __syncthreads();

        if (isg0) {
            float ai[3][4], ghl[3][4];
            xproj_lane(sh_x, sh_wi, w, lane, ai);
            const float* gp = gates + (w * 32 + lane) * 12;
            #pragma unroll
            for (int nf = 0; nf < 3; nf++)
                #pragma unroll
                for (int i = 0; i < 4; i++) ghl[nf][i] = gp[nf * 4 + i];
            upd_lane(ai, ghl, sb_b0, u0, w, lane,
                     g_A1[rb][0], g_A1[rb][1], g_A1[wb][0], g_A1[wb][1]);
        }
        gbar();

        if (isg0) fc_phase(g_A1[wb][0], g_A1[wb][1], fcW, fcb,
                           out + (long)(s + 1) * BB * LL);
        gbar();
    }
}

extern "C" void kernel_launch(void* const* d_in, const int* in_sizes, int n_in,
                              void* d_out, int out_size) {
    const float* feats  = (const float*)d_in[0];
    const float* labels = (const float*)d_in[1];
    const float* y      = (const float*)d_in[2];
    const int*   teach  = (const int*)d_in[3];
    const float* eWih0  = (const float*)d_in[4];
    const float* eWhh0  = (const float*)d_in[5];
    const float* ebih0  = (const float*)d_in[6];
    const float* ebhh0  = (const float*)d_in[7];
    const float* eWih1  = (const float*)d_in[8];
    const float* eWhh1  = (const float*)d_in[9];
    const float* ebih1  = (const float*)d_in[10];
    const float* ebhh1  = (const float*)d_in[11];
    const float* dWih   = (const float*)d_in[12];
    const float* dWhh   = (const float*)d_in[13];
    const float* dbih   = (const float*)d_in[14];
    const float* dbhh   = (const float*)d_in[15];
    const float* fcW    = (const float*)d_in[16];
    const float* fcb    = (const float*)d_in[17];
    float* out = (float*)d_out;

    static int smem_set = 0;
    if (!smem_set) {
        cudaFuncSetAttribute(gru_persistent,
                             cudaFuncAttributeMaxDynamicSharedMemorySize, 138240);
        smem_set = 1;
    }

    gru_persistent<<<NBLK, NTHR, 138240>>>(feats, labels, y, teach,
                                           eWih0, eWhh0, ebih0, ebhh0,
                                           eWih1, eWhh1, ebih1, ebhh1,
                                           dWih, dWhh, dbih, dbhh,
                                           fcW, fcb, out);
}

// round 13
// speedup vs baseline: 1.1384x; 1.1384x over previous
#include <cuda_runtime.h>
#include <cuda_bf16.h>

#define NBLK 128
#define NTHR 768
#define BB   128
#define TT   512
#define PREDN 24
#define FF   16
#define LL   8
#define HH   1024
#define FROWS (TT + PREDN - 1)

typedef unsigned int uint;

// ---------------- persistent device scratch ---------------------------------
__device__ uint4 g_A0[2][2][8 * 64 * 32];   // hidden states, MMA A-frag order
__device__ uint4 g_A1[2][2][8 * 64 * 32];
__device__ uint4 g_B[4][NBLK][3][32][2][32]; // [mat][bid][nf][hc][pl][ln]
__device__ float g_p[BB * LL];
__device__ unsigned g_count = 0;
__device__ unsigned g_gen = 0;

// ---------------- grid barrier ----------------------------------------------
__device__ __forceinline__ void gbar() {
    __syncthreads();
    if (threadIdx.x == 0) {
        __threadfence();
        volatile unsigned* vg = &g_gen;
        unsigned g = *vg;
        if (atomicAdd(&g_count, 1u) == NBLK - 1) {
            g_count = 0;
            __threadfence();
            *vg = g + 1;
        } else {
            while (*vg == g) {}
        }
        __threadfence();
    }
    __syncthreads();
}

// named barrier for one 256-thread group (ids 1..3)
__device__ __forceinline__ void barg(int id) {
    asm volatile("bar.sync %0, 256;" :: "r"(id) : "memory");
}

// ---------------- 2B coherent global ld/st ----------------------------------
__device__ __forceinline__ unsigned short ldcg_u16(const void* p) {
    unsigned short v;
    asm volatile("ld.global.cg.u16 %0, [%1];" : "=h"(v) : "l"(p));
    return v;
}
__device__ __forceinline__ void stcg_u16(void* p, unsigned short v) {
    asm volatile("st.global.cg.u16 [%0], %1;" :: "l"(p), "h"(v));
}

// ---------------- h element <-> fragment-layout mapping ----------------------
__device__ __forceinline__ int h_off(int b, int u) {
    int rg = b >> 4, r = b & 15, kp = u & 15, kg = u >> 4;
    int ireg = (r >> 3) + ((kp >> 3) << 1);
    int ln = (r & 7) * 4 + ((kp & 7) >> 1);
    return ((rg * 64 + kg) * 32 + ln) * 16 + ireg * 4 + (kp & 1) * 2;
}
__device__ __forceinline__ void store_h(uint4* Ph, uint4* Pl, int b, int u, float v) {
    __nv_bfloat16 hi = __float2bfloat16(v);
    __nv_bfloat16 lo = __float2bfloat16(v - __bfloat162float(hi));
    int off = h_off(b, u);
    stcg_u16((char*)Ph + off, __bfloat16_as_ushort(hi));
    stcg_u16((char*)Pl + off, __bfloat16_as_ushort(lo));
}
__device__ __forceinline__ float load_h(const uint4* Ph, const uint4* Pl, int b, int u) {
    int off = h_off(b, u);
    float hi = __bfloat162float(__ushort_as_bfloat16(ldcg_u16((const char*)Ph + off)));
    float lo = __bfloat162float(__ushort_as_bfloat16(ldcg_u16((const char*)Pl + off)));
    return hi + lo;
}

// ---------------- HMMA m16n8k16 bf16 -> f32 ----------------------------------
__device__ __forceinline__ void mma16816(float* c, const uint* a, uint b0, uint b1) {
    asm volatile(
        "mma.sync.aligned.m16n8k16.row.col.f32.bf16.bf16.f32 "
        "{%0,%1,%2,%3}, {%4,%5,%6,%7}, {%8,%9}, {%0,%1,%2,%3};"
        : "+f"(c[0]), "+f"(c[1]), "+f"(c[2]), "+f"(c[3])
        : "r"(a[0]), "r"(a[1]), "r"(a[2]), "r"(a[3]), "r"(b0), "r"(b1));
}

// ---------------- cp.async staging: one ring slot = 4 hc = 768 uint4 ----------
__device__ __forceinline__ void issue3(const uint4* __restrict__ B,
                                       const int* offs, int hc0, uint dst, int s) {
    const uint4* base = B + hc0 * 64;
    uint d = dst + s * 48;
    #pragma unroll
    for (int j = 0; j < 3; j++)
        asm volatile("cp.async.cg.shared.global [%0], [%1], 16;"
                     :: "r"(d + j * 16), "l"(base + offs[j]) : "memory");
    asm volatile("cp.async.commit_group;" ::: "memory");
}

// ---------------- single GEMM engine (one group of 8 warps) -------------------
// Warp wg: rows [16wg,16wg+16), all 24 cols, K=1024; 576-MMA chain.
// A: depth-2 register pipeline (ldcg). B: own smem 3-slot ring, own named bar.
__device__ void gemm3(const uint4* __restrict__ Ah, const uint4* __restrict__ Al,
                      const uint4* __restrict__ Bsrc, const int* offs,
                      uint4* __restrict__ ring, uint ring_addr,
                      int wg, int lane, int s, int barid, float acc[3][4]) {
    #pragma unroll
    for (int nf = 0; nf < 3; nf++)
        #pragma unroll
        for (int i = 0; i < 4; i++) acc[nf][i] = 0.f;

    const uint4* Abh = Ah + wg * 2048 + lane;
    const uint4* Abl = Al + wg * 2048 + lane;

    barg(barid);                       // ring free (this group consumed it)
    issue3(Bsrc, offs, 0, ring_addr, s);
    issue3(Bsrc, offs, 4, ring_addr + 12288, s);

    uint4 fah[2][2], fal[2][2];
    #pragma unroll
    for (int d = 0; d < 2; d++) {
        fah[d][0] = __ldcg(Abh + d * 64);   fah[d][1] = __ldcg(Abh + d * 64 + 32);
        fal[d][0] = __ldcg(Abl + d * 64);   fal[d][1] = __ldcg(Abl + d * 64 + 32);
    }

    #pragma unroll 1
    for (int g = 0; g < 8; g++) {
        asm volatile("cp.async.wait_group 1;" ::: "memory");
        barg(barid);
        if (g + 2 < 8)
            issue3(Bsrc, offs, (g + 2) * 4, ring_addr + ((g + 2) % 3) * 12288, s);
        else
            asm volatile("cp.async.commit_group;" ::: "memory");
        const uint4* sbuf = ring + (g % 3) * 768;
        #pragma unroll
        for (int j = 0; j < 4; j++) {
            int hc = 4 * g + j;
            int d = hc & 1;
            #pragma unroll
            for (int nf = 0; nf < 3; nf++) {
                uint4 BH = sbuf[(j * 6 + nf * 2) * 32 + lane];
                uint4 BL = sbuf[(j * 6 + nf * 2 + 1) * 32 + lane];
                const uint* a0h = (const uint*)&fah[d][0];
                const uint* a0l = (const uint*)&fal[d][0];
                const uint* a1h = (const uint*)&fah[d][1];
                const uint* a1l = (const uint*)&fal[d][1];
                mma16816(acc[nf], a0h, BH.x, BH.y);
                mma16816(acc[nf], a0l, BH.x, BH.y);
                mma16816(acc[nf], a0h, BL.x, BL.y);
                mma16816(acc[nf], a1h, BH.z, BH.w);
                mma16816(acc[nf], a1l, BH.z, BH.w);
                mma16816(acc[nf], a1h, BL.z, BL.w);
            }
            int nhc = hc + 2;
            if (nhc < 32) {
                fah[d][0] = __ldcg(Abh + nhc * 64);  fah[d][1] = __ldcg(Abh + nhc * 64 + 32);
                fal[d][0] = __ldcg(Abl + nhc * 64);  fal[d][1] = __ldcg(Abl + nhc * 64 + 32);
            }
        }
    }
}

// ---------------- GRU pieces (per MMA lane) ------------------------------------
__device__ __forceinline__ float sigf(float x) { return 1.f / (1.f + __expf(-x)); }

__device__ __forceinline__ void preload_ho(const uint4* Ph, const uint4* Pl,
                                           int u0, int wg, int lane, float ho[4]) {
    int r0 = wg * 16 + (lane >> 2);
    int c2 = (lane & 3) * 2;
    #pragma unroll
    for (int i = 0; i < 4; i++) {
        int b = r0 + (i >> 1) * 8;
        int jc = u0 + c2 + (i & 1);
        ho[i] = load_h(Ph, Pl, b, jc);
    }
}

// sb: per-u bias table {bir+bhr, biz+bhz, bin, bhn} x 8 u-columns
__device__ __forceinline__ void upd_pre(const float gi[3][4], const float gh[3][4],
                                        const float* __restrict__ sb, const float ho[4],
                                        int u0, int wg, int lane,
                                        uint4* Phn, uint4* Pln) {
    int r0 = wg * 16 + (lane >> 2);
    int c2 = (lane & 3) * 2;
    #pragma unroll
    for (int i = 0; i < 4; i++) {
        int b = r0 + (i >> 1) * 8;
        int q = i & 1;
        int jc = u0 + c2 + q;
        const float* bv = sb + (c2 + q) * 4;
        float r = sigf(gi[0][i] + gh[0][i] + bv[0]);
        float z = sigf(gi[1][i] + gh[1][i] + bv[1]);
        float n = tanhf(gi[2][i] + bv[2] + r * (gh[2][i] + bv[3]));
        store_h(Phn, Pln, b, jc, (1.f - z) * n + z * ho[i]);
    }
}

__device__ __forceinline__ void xproj_lane(const float* __restrict__ sh_x,
                                           const float* __restrict__ sh_wi,
                                           int wg, int lane, float ai[3][4]) {
    int r0 = wg * 16 + (lane >> 2);
    int c2 = (lane & 3) * 2;
    #pragma unroll
    for (int i = 0; i < 4; i++) {
        int b = r0 + (i >> 1) * 8;
        int u = c2 + (i & 1);
        float a0 = 0.f, a1 = 0.f, a2 = 0.f;
        #pragma unroll
        for (int k = 0; k < 24; k++) {
            float xv = sh_x[b * 25 + k];
            a0 += xv * sh_wi[k * 24 + u];
            a1 += xv * sh_wi[k * 24 + 8 + u];
            a2 += xv * sh_wi[k * 24 + 16 + u];
        }
        ai[0][i] = a0; ai[1][i] = a1; ai[2][i] = a2;
    }
}

// ---------------- misc helpers --------------------------------------------------
__device__ __forceinline__ void load_wi_slice(const float* __restrict__ Wih, int u0,
                                              float* __restrict__ sh_wi) {
    for (int idx = threadIdx.x; idx < 24 * 24; idx += NTHR) {
        int jl = idx / 24, k = idx % 24;
        int g = jl >> 3, uu = jl & 7;
        sh_wi[k * 24 + jl] = Wih[(long)(g * HH + u0 + uu) * 24 + k];
    }
}

__device__ __forceinline__ void fill_bias(const float* __restrict__ bih,
                                          const float* __restrict__ bhh,
                                          int u0, int uu, float* __restrict__ sb) {
    int jc = u0 + uu;
    sb[uu * 4 + 0] = bih[jc] + bhh[jc];
    sb[uu * 4 + 1] = bih[HH + jc] + bhh[HH + jc];
    sb[uu * 4 + 2] = bih[2 * HH + jc];
    sb[uu * 4 + 3] = bhh[2 * HH + jc];
}

__device__ __forceinline__ void fc_phase(const uint4* Ph, const uint4* Pl,
                                         const float* __restrict__ fcW,
                                         const float* __restrict__ fcb,
                                         float* __restrict__ outp) {
    int b = blockIdx.x;
    int w = threadIdx.x >> 5;
    int lane = threadIdx.x & 31;
    float s = 0.f;
    #pragma unroll
    for (int c = 0; c < 32; c++) {
        int u = c * 32 + lane;
        s += load_h(Ph, Pl, b, u) * fcW[(long)w * HH + u];
    }
    #pragma unroll
    for (int o = 16; o; o >>= 1) s += __shfl_down_sync(0xffffffffu, s, o);
    if (lane == 0) {
        float v = s + fcb[w];
        outp[b * LL + w] = v;
        asm volatile("st.global.cg.f32 [%0], %1;" :: "l"(g_p + b * LL + w), "f"(v));
    }
}

// ---------------- persistent kernel -----------------------------------------
__global__ void __launch_bounds__(NTHR, 1) gru_persistent(
    const float* __restrict__ feats, const float* __restrict__ labels,
    const float* __restrict__ y, const int* __restrict__ teacher,
    const float* __restrict__ eWih0, const float* __restrict__ eWhh0,
    const float* __restrict__ ebih0, const float* __restrict__ ebhh0,
    const float* __restrict__ eWih1, const float* __restrict__ eWhh1,
    const float* __restrict__ ebih1, const float* __restrict__ ebhh1,
    const float* __restrict__ dWih, const float* __restrict__ dWhh,
    const float* __restrict__ dbih, const float* __restrict__ dbhh,
    const float* __restrict__ fcW, const float* __restrict__ fcb,
    float* __restrict__ out)
{
    extern __shared__ __align__(16) unsigned char smem_raw[];
    uint4* rings = (uint4*)smem_raw;                        // 3 x 36864 = 110592 B
    float* gates = (float*)(smem_raw + 110592);             // 12288 B (gh1 exchange)
    float* sh_x  = (float*)(smem_raw + 122880);             // 12800 B
    float* sh_wi = (float*)(smem_raw + 135680);             // 2304 B
    float* sb_b0 = (float*)(smem_raw + 137984);             // 128 B (enc layer0)
    float* sb_b1 = (float*)(smem_raw + 138112);             // 128 B (enc layer1)
    float* sb_bd = (float*)(smem_raw + 138240);             // 128 B (decoder)

    const int t = threadIdx.x;
    const int lane = t & 31;
    const int grp = t >> 8;              // 0,1,2
    const int s = t & 255;               // index within group
    const int wg = (t >> 5) & 7;         // warp within group
    const int u0 = blockIdx.x * 8;
    const int teach = teacher[0];

    uint4* ring = rings + grp * 2304;    // 2304 uint4 = 36864 B per group
    const uint ring_addr = (uint)__cvta_generic_to_shared(ring);
    const int barid = grp + 1;

    // per-thread cp.async source offsets (3 per thread, within matrix slice)
    int offs[3];
    #pragma unroll
    for (int j = 0; j < 3; j++) {
        int li = s * 3 + j;
        int ln = li & 31;
        int q = li >> 5;          // 0..23
        int sub = q % 6;
        int hcg = q / 6;          // 0..3
        int nf = sub >> 1, pl = sub & 1;
        offs[j] = nf * 2048 + hcg * 64 + pl * 32 + ln;
    }

    const uint4* Bb0 = &g_B[0][blockIdx.x][0][0][0][0];   // eWhh0
    const uint4* Bb1 = &g_B[1][blockIdx.x][0][0][0][0];   // eWih1
    const uint4* Bb2 = &g_B[2][blockIdx.x][0][0][0][0];   // eWhh1
    const uint4* Bb3 = &g_B[3][blockIdx.x][0][0][0][0];   // dWhh

    // ---- zero h1 buffer 0 (h1(-1) = 0), both planes ----
    {
        int gid = blockIdx.x * NTHR + t;
        if (gid < 32768) ((uint4*)g_A1)[gid] = make_uint4(0, 0, 0, 0);
    }

    // ---- split + permute weights into fragment order (per-block slice) ----
    {
        const float* Wm[4] = {eWhh0, eWih1, eWhh1, dWhh};
        for (int wdx = t; wdx < 4 * 3 * 32 * 2 * 32; wdx += NTHR) {
            int ln = wdx & 31;
            int pl = (wdx >> 5) & 1;
            int hc = (wdx >> 6) & 31;
            int rest = wdx >> 11;
            int nw = rest % 3, m = rest / 3;
            const float* W = Wm[m];
            int u = ln >> 2;
            long wr = (long)(nw * HH + u0 + u) * HH;
            uint vals[4];
            #pragma unroll
            for (int c = 0; c < 4; c++) {
                int k0 = hc * 32 + (c >> 1) * 16 + (c & 1) * 8 + (ln & 3) * 2;
                float2 xv = *reinterpret_cast<const float2*>(W + wr + k0);
                __nv_bfloat16 h0 = __float2bfloat16(xv.x);
                __nv_bfloat16 h1 = __float2bfloat16(xv.y);
                if (pl) {
                    h0 = __float2bfloat16(xv.x - __bfloat162float(h0));
                    h1 = __float2bfloat16(xv.y - __bfloat162float(h1));
                }
                vals[c] = (uint)__bfloat16_as_ushort(h0) |
                          ((uint)__bfloat16_as_ushort(h1) << 16);
            }
            g_B[m][blockIdx.x][nw][hc][pl][ln] = make_uint4(vals[0], vals[1], vals[2], vals[3]);
        }
    }
    load_wi_slice(eWih0, u0, sh_wi);
    if (t < 8)                 fill_bias(ebih0, ebhh0, u0, t, sb_b0);
    else if (t < 16)           fill_bias(ebih1, ebhh1, u0, t - 8, sb_b1);
    else if (t < 24)           fill_bias(dbih, dbhh, u0, t - 16, sb_bd);

    // ---- prologue: h0(0) = GRU(x(0), h=0) -> g_A0[0] ----
    for (int idx = t; idx < BB * 24; idx += NTHR) {
        int b = idx / 24, k = idx % 24;
        sh_x[b * 25 + k] = (k < FF) ? feats[((long)b * FROWS) * FF + k]
                                    : labels[((long)b * TT) * LL + (k - FF)];
    }
    __syncthreads();
    if (grp == 2) {
        float xp[3][4], zg[3][4], zho[4] = {0.f, 0.f, 0.f, 0.f};
        #pragma unroll
        for (int g = 0; g < 3; g++)
            #pragma unroll
            for (int i = 0; i < 4; i++) zg[g][i] = 0.f;
        xproj_lane(sh_x, sh_wi, wg, lane, xp);
        upd_pre(xp, zg, sb_b0, zho, u0, wg, lane, g_A0[0][0], g_A0[0][1]);
    }
    gbar();

    // ================= encoder: 3 independent GEMM groups, 1 gbar/step ========
    for (int step = 0; step < TT; step++) {
        int rb = step & 1, wb = rb ^ 1;

        if (step + 1 < TT) {
            for (int idx = t; idx < BB * 24; idx += NTHR) {
                int b = idx / 24, k = idx % 24;
                sh_x[b * 25 + k] = (k < FF) ? feats[((long)b * FROWS + step + 1) * FF + k]
                                            : labels[((long)b * TT + step + 1) * LL + (k - FF)];
            }
        }

        float acc[3][4];
        float ho[4];
        if (grp == 0) {
            // gi1 = Wih1 . h0(step); also prefetch h1_old for the update
            preload_ho(g_A1[rb][0], g_A1[rb][1], u0, wg, lane, ho);
            gemm3(g_A0[rb][0], g_A0[rb][1], Bb1, offs, ring, ring_addr,
                  wg, lane, s, barid, acc);
        } else if (grp == 1) {
            // gh1 = Whh1 . h1(step-1) -> post to gates
            gemm3(g_A1[rb][0], g_A1[rb][1], Bb2, offs, ring, ring_addr,
                  wg, lane, s, barid, acc);
            float* gp = gates + (wg * 32 + lane) * 12;
            #pragma unroll
            for (int nf = 0; nf < 3; nf++)
                #pragma unroll
                for (int i = 0; i < 4; i++) gp[nf * 4 + i] = acc[nf][i];
        } else {
            // gh0 = Whh0 . h0(step) (for step+1); prefetch h0_old
            preload_ho(g_A0[rb][0], g_A0[rb][1], u0, wg, lane, ho);
            gemm3(g_A0[rb][0], g_A0[rb][1], Bb0, offs, ring, ring_addr,
                  wg, lane, s, barid, acc);
        }
        __syncthreads();

        if (grp == 0) {
            float ghl[3][4];
            const float* gp = gates + (wg * 32 + lane) * 12;
            #pragma unroll
            for (int nf = 0; nf < 3; nf++)
                #pragma unroll
                for (int i = 0; i < 4; i++) ghl[nf][i] = gp[nf * 4 + i];
            // h1(step) = GRU(gi=acc, gh=ghl, h1_old)
            upd_pre(acc, ghl, sb_b1, ho, u0, wg, lane, g_A1[wb][0], g_A1[wb][1]);
        } else if (grp == 2 && step + 1 < TT) {
            float xp[3][4];
            xproj_lane(sh_x, sh_wi, wg, lane, xp);
            // h0(step+1) = GRU(xp, gh=acc, h0_old)
            upd_pre(xp, acc, sb_b0, ho, u0, wg, lane, g_A0[wb][0], g_A0[wb][1]);
        }
        gbar();
    }

    // ps -> out[0] + seed g_p (final h1 in buffer 0)
    if (t < 256) fc_phase(g_A1[0][0], g_A1[0][1], fcW, fcb, out);
    load_wi_slice(dWih, u0, sh_wi);
    gbar();

    // ================= decoder (group 1 does everything) =====================
    for (int sdx = 0; sdx < PREDN - 1; sdx++) {
        int rb = sdx & 1, wb = rb ^ 1;
        for (int idx = t; idx < BB * 24; idx += NTHR) {
            int b = idx / 24, k = idx % 24;
            float v;
            if (k < FF)      v = feats[((long)b * FROWS + TT + sdx) * FF + k];
            else if (teach)  v = y[((long)b * (PREDN - 1) + sdx) * LL + (k - FF)];
            else             v = __ldcg(g_p + b * LL + (k - FF));
            sh_x[b * 25 + k] = v;
        }

        float acc[3][4];
        float ho[4];
        if (grp == 1) {
            preload_ho(g_A1[rb][0], g_A1[rb][1], u0, wg, lane, ho);
            gemm3(g_A1[rb][0], g_A1[rb][1], Bb3, offs, ring, ring_addr,
                  wg, lane, s, barid, acc);
        }
        __syncthreads();

        if (grp == 1) {
            float xp[3][4];
            xproj_lane(sh_x, sh_wi, wg, lane, xp);
            upd_pre(xp, acc, sb_bd, ho, u0, wg, lane, g_A1[wb][0], g_A1[wb][1]);
        }
        gbar();

        if (t < 256) fc_phase(g_A1[wb][0], g_A1[wb][1], fcW, fcb,
                              out + (long)(sdx + 1) * BB * LL);
        gbar();
    }
}

extern "C" void kernel_launch(void* const* d_in, const int* in_sizes, int n_in,
                              void* d_out, int out_size) {
    const float* feats  = (const float*)d_in[0];
    const float* labels = (const float*)d_in[1];
    const float* y      = (const float*)d_in[2];
    const int*   teach  = (const int*)d_in[3];
    const float* eWih0  = (const float*)d_in[4];
    const float* eWhh0  = (const float*)d_in[5];
    const float* ebih0  = (const float*)d_in[6];
    const float* ebhh0  = (const float*)d_in[7];
    const float* eWih1  = (const float*)d_in[8];
    const float* eWhh1  = (const float*)d_in[9];
    const float* ebih1  = (const float*)d_in[10];
    const float* ebhh1  = (const float*)d_in[11];
    const float* dWih   = (const float*)d_in[12];
    const float* dWhh   = (const float*)d_in[13];
    const float* dbih   = (const float*)d_in[14];
    const float* dbhh   = (const float*)d_in[15];
    const float* fcW    = (const float*)d_in[16];
    const float* fcb    = (const float*)d_in[17];
    float* out = (float*)d_out;

    static int smem_set = 0;
    if (!smem_set) {
        cudaFuncSetAttribute(gru_persistent,
                             cudaFuncAttributeMaxDynamicSharedMemorySize, 138368);
        smem_set = 1;
    }

    gru_persistent<<<NBLK, NTHR, 138368>>>(feats, labels, y, teach,
                                           eWih0, eWhh0, ebih0, ebhh0,
                                           eWih1, eWhh1, ebih1, ebhh1,
                                           dWih, dWhh, dbih, dbhh,
                                           fcW, fcb, out);
}